// round 12
// baseline (speedup 1.0000x reference)
#include <cuda_runtime.h>
#include <cstdint>
#include <math.h>

#define NB    128
#define H     128
#define NPG   8
#define BT    3
#define AA    243
#define PAIRS 192
#define ABST  132

typedef unsigned long long u64;

__device__ __forceinline__ u64 pack2(float lo, float hi) {
    u64 r; asm("mov.b64 %0, {%1, %2};" : "=l"(r) : "f"(lo), "f"(hi)); return r;
}
__device__ __forceinline__ void fma2(u64& d, u64 a, u64 b) {
    asm("fma.rn.f32x2 %0, %1, %2, %0;" : "+l"(d) : "l"(a), "l"(b));
}
__device__ __forceinline__ float2 unpack2(u64 v) {
    float2 f; asm("mov.b64 {%0, %1}, %2;" : "=f"(f.x), "=f"(f.y) : "l"(v)); return f;
}

// AB scratch: [graph][grp][node][h]  (1 MB device-global)
__device__ float ABg[NB * 2 * NPG * H];

// ---------------- K1: Ai/Bj GEMM -> ABg (primary) ----------------
__global__ __launch_bounds__(256, 3)
void apm_gemm_kernel(const float* __restrict__ nf,
                     const float* __restrict__ Wa2)
{
    // allow the dependent (tail) grid to start its prelude immediately
    asm volatile("griddepcontrol.launch_dependents;" ::: "memory");

    const int b   = blockIdx.x >> 1;
    const int grp = blockIdx.x & 1;
    const int t   = threadIdx.x;

    __shared__ __align__(16) u64 ps[H][4];    // [c][node-pair]

    const int h = t & 127;
    const int X = t >> 7;                     // node quad 4X..4X+3
    const float* Wp = Wa2 + grp * H * H + h;

    float Wr[32];
    #pragma unroll
    for (int i = 0; i < 32; i++) Wr[i] = Wp[i * H];   // batch 0 pre-barrier

    #pragma unroll
    for (int idx = t; idx < 4 * H; idx += 256) {
        int nh = idx >> 7, c = idx & 127;
        float v0 = fmaxf(nf[(b * NPG + 2 * nh)     * H + c], 0.f);
        float v1 = fmaxf(nf[(b * NPG + 2 * nh + 1) * H + c], 0.f);
        ps[c][nh] = pack2(v0, v1);
    }
    __syncthreads();

    u64 acc0 = 0, acc1 = 0;                   // node pairs 2X, 2X+1
    #pragma unroll
    for (int batch = 0; batch < 4; batch++) {
        if (batch) {
            #pragma unroll
            for (int i = 0; i < 32; i++) Wr[i] = Wp[(batch * 32 + i) * H];
        }
        #pragma unroll
        for (int cc = 0; cc < 32; cc++) {
            const int c = batch * 32 + cc;
            u64 wp = pack2(Wr[cc], Wr[cc]);
            ulonglong2 q = *reinterpret_cast<const ulonglong2*>(&ps[c][X * 2]);
            fma2(acc0, q.x, wp);
            fma2(acc1, q.y, wp);
        }
    }
    float2 f0 = unpack2(acc0);
    float2 f1 = unpack2(acc1);
    float* dst = ABg + ((b * 2 + grp) * NPG) * H;
    dst[(4 * X + 0) * H + h] = f0.x;
    dst[(4 * X + 1) * H + h] = f0.y;
    dst[(4 * X + 2) * H + h] = f1.x;
    dst[(4 * X + 3) * H + h] = f1.y;
}

// ---------------- K2: prelude || K1, then scores + softmax ----------------
__global__ __launch_bounds__(256, 3)
void apm_tail_kernel(const float* __restrict__ nf,
                     const float* __restrict__ mask,
                     const float* __restrict__ Wfcv1,
                     const float* __restrict__ bfcv1,
                     const float* __restrict__ Wfcv2,
                     const float* __restrict__ bfcv2,
                     const float* __restrict__ ba2,
                     const float* __restrict__ Wfin,
                     const float* __restrict__ bfin,
                     const int*   __restrict__ idxmask,
                     float* __restrict__ out)
{
    const int b = blockIdx.x;
    const int t = threadIdx.x;

    __shared__ __align__(16) float ABs[2][NPG][ABST];
    __shared__ __align__(16) float sWfT[BT][H];
    __shared__ __align__(16) float sba[H];
    __shared__ __align__(16) float ssum[H];
    __shared__ float sc[PAIRS];
    __shared__ int   sidx[AA];
    __shared__ float smk[AA];
    __shared__ float red[2];

    // ======== PRELUDE: everything independent of ABg (overlaps K1) ========
    if (t < AA) {
        sidx[t] = idxmask[b * AA + t];
        smk[t]  = mask[b * AA + t];
    }
    if (t < H) {
        float a = 0.f;
        #pragma unroll
        for (int n = 0; n < NPG; n++) a += nf[(b * NPG + n) * H + t];
        ssum[t] = a;
        sba[t]  = ba2[t];
    }
    #pragma unroll
    for (int idx = t; idx < H * BT; idx += 256) {
        int hh = idx & 127, k = idx >> 7;
        sWfT[k][hh] = Wfin[hh * BT + k];
    }
    __syncthreads();   // P1: ssum visible

    // full readout MLP in the prelude (warps 6-7)
    if (t >= 192) {
        const int j = t - 192;                // 0..63
        const float4* S4 = reinterpret_cast<const float4*>(ssum);
        float acc0 = 0.f, acc1 = 0.f;
        #pragma unroll
        for (int q = 0; q < 32; q += 2) {
            float4 sv = S4[q];
            int c = q * 4;
            acc0 += sv.x * Wfcv1[(c + 0) * 64 + j] + sv.y * Wfcv1[(c + 1) * 64 + j]
                  + sv.z * Wfcv1[(c + 2) * 64 + j] + sv.w * Wfcv1[(c + 3) * 64 + j];
            sv = S4[q + 1];
            c = (q + 1) * 4;
            acc1 += sv.x * Wfcv1[(c + 0) * 64 + j] + sv.y * Wfcv1[(c + 1) * 64 + j]
                  + sv.z * Wfcv1[(c + 2) * 64 + j] + sv.w * Wfcv1[(c + 3) * 64 + j];
        }
        float hid = fmaxf(acc0 + acc1 + bfcv1[j], 0.f) * Wfcv2[j];
        #pragma unroll
        for (int off = 16; off > 0; off >>= 1)
            hid += __shfl_down_sync(0xffffffffu, hid, off);
        if ((t & 31) == 0) red[(t >> 5) - 6] = hid;
    }

    // ======== wait for K1's ABg writes ========
    asm volatile("griddepcontrol.wait;" ::: "memory");

    // stage AB (L2-hot, 8 KB) into padded smem
    {
        const float4* src = reinterpret_cast<const float4*>(ABg + b * 2 * NPG * H);
        #pragma unroll
        for (int v = 0; v < 2; v++) {
            int g = t + v * 256;              // float4 index 0..511
            float4 val = src[g];
            int row = g >> 5;                 // grp*8+n
            int hh  = (g & 31) * 4;
            *reinterpret_cast<float4*>(&ABs[row >> 3][row & 7][hh]) = val;
        }
    }
    __syncthreads();   // S1: ABs + red visible

    // scores: t<192, one thread per score
    if (t < PAIRS) {
        const int k = t >> 6;
        const int p = t & 63;
        const int i = p >> 3, j = p & 7;
        const float4* A4 = reinterpret_cast<const float4*>(ABs[0][i]);
        const float4* B4 = reinterpret_cast<const float4*>(ABs[1][j]);
        const float4* W4 = reinterpret_cast<const float4*>(sWfT[k]);
        const float4* Z4 = reinterpret_cast<const float4*>(sba);
        float acc0 = 0.f, acc1 = 0.f;
        #pragma unroll
        for (int q = 0; q < 32; q += 2) {
            float4 a, bb, w, z;
            a = A4[q]; bb = B4[q]; w = W4[q]; z = Z4[q];
            acc0 += fmaxf(a.x + bb.x + z.x, 0.f) * w.x
                  + fmaxf(a.y + bb.y + z.y, 0.f) * w.y
                  + fmaxf(a.z + bb.z + z.z, 0.f) * w.z
                  + fmaxf(a.w + bb.w + z.w, 0.f) * w.w;
            a = A4[q + 1]; bb = B4[q + 1]; w = W4[q + 1]; z = Z4[q + 1];
            acc1 += fmaxf(a.x + bb.x + z.x, 0.f) * w.x
                  + fmaxf(a.y + bb.y + z.y, 0.f) * w.y
                  + fmaxf(a.z + bb.z + z.z, 0.f) * w.z
                  + fmaxf(a.w + bb.w + z.w, 0.f) * w.w;
        }
        sc[p * BT + k] = acc0 + acc1 + bfin[k];
    }
    __syncthreads();   // S2

    // warp 0: readout store + gather + softmax
    if (t < 32) {
        if (t == 0) out[NB * AA + b] = red[0] + red[1] + bfcv2[0];

        float fv[8];
        #pragma unroll
        for (int q = 0; q < 8; q++) {
            int e = t + 32 * q;
            if (e < AA) {
                int im = sidx[e];
                fv[q] = ((im < PAIRS) ? sc[im] : 0.f) + smk[e];
            } else fv[q] = -INFINITY;
        }
        float m = fv[0];
        #pragma unroll
        for (int q = 1; q < 8; q++) m = fmaxf(m, fv[q]);
        #pragma unroll
        for (int off = 16; off > 0; off >>= 1)
            m = fmaxf(m, __shfl_xor_sync(0xffffffffu, m, off));
        float sr = 0.f;
        #pragma unroll
        for (int q = 0; q < 8; q++) {
            fv[q] = (fv[q] == -INFINITY) ? 0.f : __expf(fv[q] - m);
            sr += fv[q];
        }
        #pragma unroll
        for (int off = 16; off > 0; off >>= 1)
            sr += __shfl_xor_sync(0xffffffffu, sr, off);
        float inv = 1.f / sr;
        #pragma unroll
        for (int q = 0; q < 8; q++) {
            int e = t + 32 * q;
            if (e < AA) out[b * AA + e] = fv[q] * inv;
        }
    }
}

extern "C" void kernel_launch(void* const* d_in, const int* in_sizes, int n_in,
                              void* d_out, int out_size) {
    const float* nf     = (const float*)d_in[0];
    const float* mask   = (const float*)d_in[2];
    const float* Wfcv1  = (const float*)d_in[3];
    const float* bfcv1  = (const float*)d_in[4];
    const float* Wfcv2  = (const float*)d_in[5];
    const float* bfcv2  = (const float*)d_in[6];
    const float* Wa2    = (const float*)d_in[7];
    const float* ba2    = (const float*)d_in[8];
    const float* Wfin   = (const float*)d_in[9];
    const float* bfin   = (const float*)d_in[10];
    const int*   idxm   = (const int*)d_in[11];
    float* out = (float*)d_out;

    apm_gemm_kernel<<<2 * NB, 256>>>(nf, Wa2);

    // tail launched with Programmatic Stream Serialization: starts during K1,
    // griddepcontrol.wait provides the ABg dependency.
    cudaLaunchConfig_t cfg = {};
    cfg.gridDim  = dim3(NB, 1, 1);
    cfg.blockDim = dim3(256, 1, 1);
    cfg.dynamicSmemBytes = 0;
    cfg.stream = 0;
    cudaLaunchAttribute attr[1];
    attr[0].id = cudaLaunchAttributeProgrammaticStreamSerialization;
    attr[0].val.programmaticStreamSerializationAllowed = 1;
    cfg.attrs = attr;
    cfg.numAttrs = 1;
    cudaLaunchKernelEx(&cfg, apm_tail_kernel,
                       nf, mask, Wfcv1, bfcv1, Wfcv2, bfcv2,
                       ba2, Wfin, bfin, idxm, out);
}

// round 13
// speedup vs baseline: 1.1272x; 1.1272x over previous
#include <cuda_runtime.h>
#include <cstdint>
#include <math.h>

#define NB    128
#define H     128
#define NPG   8
#define BT    3
#define AA    243
#define PAIRS 192
#define ABST  132

typedef unsigned long long u64;

__device__ __forceinline__ u64 pack2(float lo, float hi) {
    u64 r; asm("mov.b64 %0, {%1, %2};" : "=l"(r) : "f"(lo), "f"(hi)); return r;
}
__device__ __forceinline__ void fma2(u64& d, u64 a, u64 b) {
    asm("fma.rn.f32x2 %0, %1, %2, %0;" : "+l"(d) : "l"(a), "l"(b));
}
__device__ __forceinline__ float2 unpack2(u64 v) {
    float2 f; asm("mov.b64 {%0, %1}, %2;" : "=f"(f.x), "=f"(f.y) : "l"(v)); return f;
}

// global scratch (allocation-free): AB halves + per-graph arrival counters
__device__ float ABg[NB * 2 * NPG * H];
__device__ int   done_cnt[NB];               // zero-initialized; reset each run by winner

__global__ __launch_bounds__(256, 2)
void apm_fused_kernel(const float* __restrict__ nf,
                      const float* __restrict__ mask,
                      const float* __restrict__ Wfcv1,
                      const float* __restrict__ bfcv1,
                      const float* __restrict__ Wfcv2,
                      const float* __restrict__ bfcv2,
                      const float* __restrict__ Wa2,
                      const float* __restrict__ ba2,
                      const float* __restrict__ Wfin,
                      const float* __restrict__ bfin,
                      const int*   __restrict__ idxmask,
                      float* __restrict__ out)
{
    const int b   = blockIdx.x >> 1;
    const int grp = blockIdx.x & 1;
    const int t   = threadIdx.x;

    __shared__ __align__(16) u64   ps[H][4];           // [c][node-pair]
    __shared__ __align__(16) float ABown[NPG][ABST];   // this CTA's grp half
    __shared__ __align__(16) float ABpeer[NPG][ABST];  // peer half (filled by winner)
    __shared__ __align__(16) float sWfT[BT][H];
    __shared__ __align__(16) float sba[H];
    __shared__ __align__(16) float ssum[H];
    __shared__ float sc[PAIRS];
    __shared__ int   sidx[AA];
    __shared__ float smk[AA];
    __shared__ float red[2];
    __shared__ int   sflag;

    // ---- entry staging: cold tail inputs overlap the GEMM ----
    if (t < AA) {
        sidx[t] = idxmask[b * AA + t];
        smk[t]  = mask[b * AA + t];
    }

    const int h = t & 127;
    const int X = t >> 7;                      // node quad 4X..4X+3
    const float* Wp = Wa2 + grp * H * H + h;

    float Wr[32];
    #pragma unroll
    for (int i = 0; i < 32; i++) Wr[i] = Wp[i * H];    // batch 0 pre-barrier

    #pragma unroll
    for (int idx = t; idx < 4 * H; idx += 256) {
        int nh = idx >> 7, c = idx & 127;
        float v0 = fmaxf(nf[(b * NPG + 2 * nh)     * H + c], 0.f);
        float v1 = fmaxf(nf[(b * NPG + 2 * nh + 1) * H + c], 0.f);
        ps[c][nh] = pack2(v0, v1);
    }
    __syncthreads();   // S1

    // ---- half-GEMM (identical to the proven R11 K1) ----
    {
        u64 acc0 = 0, acc1 = 0;                // node pairs 2X, 2X+1
        #pragma unroll
        for (int batch = 0; batch < 4; batch++) {
            if (batch) {
                #pragma unroll
                for (int i = 0; i < 32; i++) Wr[i] = Wp[(batch * 32 + i) * H];
            }
            #pragma unroll
            for (int cc = 0; cc < 32; cc++) {
                const int c = batch * 32 + cc;
                u64 wp = pack2(Wr[cc], Wr[cc]);
                ulonglong2 q = *reinterpret_cast<const ulonglong2*>(&ps[c][X * 2]);
                fma2(acc0, q.x, wp);
                fma2(acc1, q.y, wp);
            }
        }
        float2 f0 = unpack2(acc0);
        float2 f1 = unpack2(acc1);
        // keep in smem for the (potential) tail ...
        ABown[4 * X + 0][h] = f0.x;
        ABown[4 * X + 1][h] = f0.y;
        ABown[4 * X + 2][h] = f1.x;
        ABown[4 * X + 3][h] = f1.y;
        // ... and publish to global for the peer
        float* dst = ABg + ((b * 2 + grp) * NPG) * H;
        dst[(4 * X + 0) * H + h] = f0.x;
        dst[(4 * X + 1) * H + h] = f0.y;
        dst[(4 * X + 2) * H + h] = f1.x;
        dst[(4 * X + 3) * H + h] = f1.y;
    }
    __threadfence();    // each thread's ABg stores visible GPU-wide
    __syncthreads();    // all threads' stores+fences done

    if (t == 0) sflag = atomicAdd(&done_cnt[b], 1);
    __syncthreads();
    if (sflag == 0) return;                    // first finisher exits, frees the SM

    // ---- winner (second finisher): reset counter, run the tail ----
    if (t == 0) done_cnt[b] = 0;               // replay-deterministic reset
    __threadfence();                           // acquire: order peer ABg reads after atomic

    // stage peer AB half (4 KB, L2-hot): one float4 per thread
    {
        const float4* src = reinterpret_cast<const float4*>(
            ABg + ((b * 2 + (grp ^ 1)) * NPG) * H);
        float4 val = src[t];                   // t = 0..255 covers 1024 floats
        int row = t >> 5;                      // node 0..7
        int hh  = (t & 31) * 4;
        *reinterpret_cast<float4*>(&ABpeer[row][hh]) = val;
    }
    // ssum + small weights (all L2-hot by now)
    if (t < H) {
        float a = 0.f;
        #pragma unroll
        for (int n = 0; n < NPG; n++) a += nf[(b * NPG + n) * H + t];
        ssum[t] = a;
        sba[t]  = ba2[t];
    }
    #pragma unroll
    for (int idx = t; idx < H * BT; idx += 256) {
        int hh = idx & 127, k = idx >> 7;
        sWfT[k][hh] = Wfin[hh * BT + k];
    }
    __syncthreads();   // S2

    // scores (t<192) + readout MLP (t 192-255)
    {
        const float (*Arows)[ABST] = (grp == 0) ? ABown : ABpeer;   // Ai = grp0
        const float (*Brows)[ABST] = (grp == 0) ? ABpeer : ABown;   // Bj = grp1
        if (t < PAIRS) {
            const int k = t >> 6;
            const int p = t & 63;
            const int i = p >> 3, j = p & 7;
            const float4* A4 = reinterpret_cast<const float4*>(Arows[i]);
            const float4* B4 = reinterpret_cast<const float4*>(Brows[j]);
            const float4* W4 = reinterpret_cast<const float4*>(sWfT[k]);
            const float4* Z4 = reinterpret_cast<const float4*>(sba);
            float acc0 = 0.f, acc1 = 0.f;
            #pragma unroll
            for (int q = 0; q < 32; q += 2) {
                float4 a, bb, w, z;
                a = A4[q]; bb = B4[q]; w = W4[q]; z = Z4[q];
                acc0 += fmaxf(a.x + bb.x + z.x, 0.f) * w.x
                      + fmaxf(a.y + bb.y + z.y, 0.f) * w.y
                      + fmaxf(a.z + bb.z + z.z, 0.f) * w.z
                      + fmaxf(a.w + bb.w + z.w, 0.f) * w.w;
                a = A4[q + 1]; bb = B4[q + 1]; w = W4[q + 1]; z = Z4[q + 1];
                acc1 += fmaxf(a.x + bb.x + z.x, 0.f) * w.x
                      + fmaxf(a.y + bb.y + z.y, 0.f) * w.y
                      + fmaxf(a.z + bb.z + z.z, 0.f) * w.z
                      + fmaxf(a.w + bb.w + z.w, 0.f) * w.w;
            }
            sc[p * BT + k] = acc0 + acc1 + bfin[k];
        } else {
            const int j = t - PAIRS;           // 0..63
            const float4* S4 = reinterpret_cast<const float4*>(ssum);
            float acc0 = 0.f, acc1 = 0.f;
            #pragma unroll
            for (int q = 0; q < 32; q += 2) {
                float4 sv = S4[q];
                int c = q * 4;
                acc0 += sv.x * Wfcv1[(c + 0) * 64 + j] + sv.y * Wfcv1[(c + 1) * 64 + j]
                      + sv.z * Wfcv1[(c + 2) * 64 + j] + sv.w * Wfcv1[(c + 3) * 64 + j];
                sv = S4[q + 1];
                c = (q + 1) * 4;
                acc1 += sv.x * Wfcv1[(c + 0) * 64 + j] + sv.y * Wfcv1[(c + 1) * 64 + j]
                      + sv.z * Wfcv1[(c + 2) * 64 + j] + sv.w * Wfcv1[(c + 3) * 64 + j];
            }
            float hid = fmaxf(acc0 + acc1 + bfcv1[j], 0.f) * Wfcv2[j];
            #pragma unroll
            for (int off = 16; off > 0; off >>= 1)
                hid += __shfl_down_sync(0xffffffffu, hid, off);
            if ((t & 31) == 0) red[(t >> 5) - 6] = hid;
        }
    }
    __syncthreads();   // S3

    // warp 0: readout store + gather + softmax
    if (t < 32) {
        if (t == 0) out[NB * AA + b] = red[0] + red[1] + bfcv2[0];

        float fv[8];
        #pragma unroll
        for (int q = 0; q < 8; q++) {
            int e = t + 32 * q;
            if (e < AA) {
                int im = sidx[e];
                fv[q] = ((im < PAIRS) ? sc[im] : 0.f) + smk[e];
            } else fv[q] = -INFINITY;
        }
        float m = fv[0];
        #pragma unroll
        for (int q = 1; q < 8; q++) m = fmaxf(m, fv[q]);
        #pragma unroll
        for (int off = 16; off > 0; off >>= 1)
            m = fmaxf(m, __shfl_xor_sync(0xffffffffu, m, off));
        float sr = 0.f;
        #pragma unroll
        for (int q = 0; q < 8; q++) {
            fv[q] = (fv[q] == -INFINITY) ? 0.f : __expf(fv[q] - m);
            sr += fv[q];
        }
        #pragma unroll
        for (int off = 16; off > 0; off >>= 1)
            sr += __shfl_xor_sync(0xffffffffu, sr, off);
        float inv = 1.f / sr;
        #pragma unroll
        for (int q = 0; q < 8; q++) {
            int e = t + 32 * q;
            if (e < AA) out[b * AA + e] = fv[q] * inv;
        }
    }
}

extern "C" void kernel_launch(void* const* d_in, const int* in_sizes, int n_in,
                              void* d_out, int out_size) {
    const float* nf     = (const float*)d_in[0];
    const float* mask   = (const float*)d_in[2];
    const float* Wfcv1  = (const float*)d_in[3];
    const float* bfcv1  = (const float*)d_in[4];
    const float* Wfcv2  = (const float*)d_in[5];
    const float* bfcv2  = (const float*)d_in[6];
    const float* Wa2    = (const float*)d_in[7];
    const float* ba2    = (const float*)d_in[8];
    const float* Wfin   = (const float*)d_in[9];
    const float* bfin   = (const float*)d_in[10];
    const int*   idxm   = (const int*)d_in[11];
    float* out = (float*)d_out;

    apm_fused_kernel<<<2 * NB, 256>>>(nf, mask, Wfcv1, bfcv1, Wfcv2, bfcv2,
                                      Wa2, ba2, Wfin, bfin, idxm, out);
}

// round 14
// speedup vs baseline: 1.2785x; 1.1342x over previous
#include <cuda_runtime.h>
#include <cstdint>
#include <math.h>

#define NB    128
#define H     128
#define NPG   8
#define BT    3
#define AA    243
#define PAIRS 192
#define ABST  132

typedef unsigned long long u64;

__device__ __forceinline__ u64 pack2(float lo, float hi) {
    u64 r; asm("mov.b64 %0, {%1, %2};" : "=l"(r) : "f"(lo), "f"(hi)); return r;
}
__device__ __forceinline__ void fma2(u64& d, u64 a, u64 b) {
    asm("fma.rn.f32x2 %0, %1, %2, %0;" : "+l"(d) : "l"(a), "l"(b));
}
__device__ __forceinline__ float2 unpack2(u64 v) {
    float2 f; asm("mov.b64 {%0, %1}, %2;" : "=f"(f.x), "=f"(f.y) : "l"(v)); return f;
}

// AB partial scratch: [chalf][graph][grp][node][h]  (2 MB device-global)
__device__ float ABp[2][NB * 2 * NPG * H];

// ---------------- K1: half-c Ai/Bj GEMM -> ABp[ch] ----------------
__global__ __launch_bounds__(256, 4)
void apm_gemm_kernel(const float* __restrict__ nf,
                     const float* __restrict__ Wa2)
{
    const int blk = blockIdx.x;                // b*4 + grp*2 + ch
    const int b   = blk >> 2;
    const int grp = (blk >> 1) & 1;
    const int ch  = blk & 1;
    const int t   = threadIdx.x;

    __shared__ __align__(16) u64 ps[64][4];    // [c-within-half][node-pair]

    const int h = t & 127;
    const int X = t >> 7;                      // node quad 4X..4X+3
    const float* Wp = Wa2 + grp * H * H + (ch * 64) * H + h;

    float Wr[32];
    #pragma unroll
    for (int i = 0; i < 32; i++) Wr[i] = Wp[i * H];    // batch 0 pre-barrier

    // stage this half's 64 c's for all 8 nodes: one entry per thread
    {
        const int c  = t & 63;
        const int nh = t >> 6;                 // node pair 0..3
        const int cg = ch * 64 + c;
        float v0 = fmaxf(nf[(b * NPG + 2 * nh)     * H + cg], 0.f);
        float v1 = fmaxf(nf[(b * NPG + 2 * nh + 1) * H + cg], 0.f);
        ps[c][nh] = pack2(v0, v1);
    }
    __syncthreads();

    u64 acc0 = 0, acc1 = 0;                    // node pairs 2X, 2X+1
    #pragma unroll
    for (int batch = 0; batch < 2; batch++) {
        if (batch) {
            #pragma unroll
            for (int i = 0; i < 32; i++) Wr[i] = Wp[(32 + i) * H];
        }
        #pragma unroll
        for (int cc = 0; cc < 32; cc++) {
            const int c = batch * 32 + cc;
            u64 wp = pack2(Wr[cc], Wr[cc]);
            ulonglong2 q = *reinterpret_cast<const ulonglong2*>(&ps[c][X * 2]);
            fma2(acc0, q.x, wp);
            fma2(acc1, q.y, wp);
        }
    }
    float2 f0 = unpack2(acc0);
    float2 f1 = unpack2(acc1);
    float* dst = ABp[ch] + ((b * 2 + grp) * NPG) * H;
    dst[(4 * X + 0) * H + h] = f0.x;
    dst[(4 * X + 1) * H + h] = f0.y;
    dst[(4 * X + 2) * H + h] = f1.x;
    dst[(4 * X + 3) * H + h] = f1.y;
}

// ---------------- K2: sum partials + scores + softmax + readout ----------------
__global__ __launch_bounds__(256, 2)
void apm_tail_kernel(const float* __restrict__ nf,
                     const float* __restrict__ mask,
                     const float* __restrict__ Wfcv1,
                     const float* __restrict__ bfcv1,
                     const float* __restrict__ Wfcv2,
                     const float* __restrict__ bfcv2,
                     const float* __restrict__ ba2,
                     const float* __restrict__ Wfin,
                     const float* __restrict__ bfin,
                     const int*   __restrict__ idxmask,
                     float* __restrict__ out)
{
    const int b = blockIdx.x;
    const int t = threadIdx.x;

    __shared__ __align__(16) float ABs[2][NPG][ABST];
    __shared__ __align__(16) float sWfT[BT][H];
    __shared__ __align__(16) float sba[H];
    __shared__ __align__(16) float ssum[H];
    __shared__ float sc[PAIRS];
    __shared__ int   sidx[AA];
    __shared__ float smk[AA];
    __shared__ float red[2];

    // stage AB = ABp[0] + ABp[1] (16 KB L2-hot): 2 summed float4 per thread
    {
        const float4* s0 = reinterpret_cast<const float4*>(ABp[0] + b * 2 * NPG * H);
        const float4* s1 = reinterpret_cast<const float4*>(ABp[1] + b * 2 * NPG * H);
        #pragma unroll
        for (int v = 0; v < 2; v++) {
            int g = t + v * 256;               // float4 index 0..511
            float4 a = s0[g];
            float4 c = s1[g];
            float4 r;
            r.x = a.x + c.x; r.y = a.y + c.y; r.z = a.z + c.z; r.w = a.w + c.w;
            int row = g >> 5;                  // grp*8+n
            int hh  = (g & 31) * 4;
            *reinterpret_cast<float4*>(&ABs[row >> 3][row & 7][hh]) = r;
        }
    }
    if (t < H) {                               // ssum + sba
        float a = 0.f;
        #pragma unroll
        for (int n = 0; n < NPG; n++) a += nf[(b * NPG + n) * H + t];
        ssum[t] = a;
        sba[t]  = ba2[t];
    }
    #pragma unroll
    for (int idx = t; idx < H * BT; idx += 256) {
        int hh = idx & 127, k = idx >> 7;
        sWfT[k][hh] = Wfin[hh * BT + k];
    }
    #pragma unroll
    for (int idx = t; idx < AA; idx += 256) {
        sidx[idx] = idxmask[b * AA + idx];
        smk[idx]  = mask[b * AA + idx];
    }
    __syncthreads();   // S1

    // scores (t<192) + readout MLP (t 192-255)
    if (t < PAIRS) {
        const int k = t >> 6;
        const int p = t & 63;
        const int i = p >> 3, j = p & 7;
        const float4* A4 = reinterpret_cast<const float4*>(ABs[0][i]);
        const float4* B4 = reinterpret_cast<const float4*>(ABs[1][j]);
        const float4* W4 = reinterpret_cast<const float4*>(sWfT[k]);
        const float4* Z4 = reinterpret_cast<const float4*>(sba);
        float acc0 = 0.f, acc1 = 0.f;
        #pragma unroll
        for (int q = 0; q < 32; q += 2) {
            float4 a, bb, w, z;
            a = A4[q]; bb = B4[q]; w = W4[q]; z = Z4[q];
            acc0 += fmaxf(a.x + bb.x + z.x, 0.f) * w.x
                  + fmaxf(a.y + bb.y + z.y, 0.f) * w.y
                  + fmaxf(a.z + bb.z + z.z, 0.f) * w.z
                  + fmaxf(a.w + bb.w + z.w, 0.f) * w.w;
            a = A4[q + 1]; bb = B4[q + 1]; w = W4[q + 1]; z = Z4[q + 1];
            acc1 += fmaxf(a.x + bb.x + z.x, 0.f) * w.x
                  + fmaxf(a.y + bb.y + z.y, 0.f) * w.y
                  + fmaxf(a.z + bb.z + z.z, 0.f) * w.z
                  + fmaxf(a.w + bb.w + z.w, 0.f) * w.w;
        }
        sc[p * BT + k] = acc0 + acc1 + bfin[k];
    } else {
        const int j = t - PAIRS;               // 0..63
        const float4* S4 = reinterpret_cast<const float4*>(ssum);
        float acc0 = 0.f, acc1 = 0.f;
        #pragma unroll
        for (int q = 0; q < 32; q += 2) {
            float4 sv = S4[q];
            int c = q * 4;
            acc0 += sv.x * Wfcv1[(c + 0) * 64 + j] + sv.y * Wfcv1[(c + 1) * 64 + j]
                  + sv.z * Wfcv1[(c + 2) * 64 + j] + sv.w * Wfcv1[(c + 3) * 64 + j];
            sv = S4[q + 1];
            c = (q + 1) * 4;
            acc1 += sv.x * Wfcv1[(c + 0) * 64 + j] + sv.y * Wfcv1[(c + 1) * 64 + j]
                  + sv.z * Wfcv1[(c + 2) * 64 + j] + sv.w * Wfcv1[(c + 3) * 64 + j];
        }
        float hid = fmaxf(acc0 + acc1 + bfcv1[j], 0.f) * Wfcv2[j];
        #pragma unroll
        for (int off = 16; off > 0; off >>= 1)
            hid += __shfl_down_sync(0xffffffffu, hid, off);
        if ((t & 31) == 0) red[(t >> 5) - 6] = hid;
    }
    __syncthreads();   // S2

    // warp 0: readout store + gather + softmax
    if (t < 32) {
        if (t == 0) out[NB * AA + b] = red[0] + red[1] + bfcv2[0];

        float fv[8];
        #pragma unroll
        for (int q = 0; q < 8; q++) {
            int e = t + 32 * q;
            if (e < AA) {
                int im = sidx[e];
                fv[q] = ((im < PAIRS) ? sc[im] : 0.f) + smk[e];
            } else fv[q] = -INFINITY;
        }
        float m = fv[0];
        #pragma unroll
        for (int q = 1; q < 8; q++) m = fmaxf(m, fv[q]);
        #pragma unroll
        for (int off = 16; off > 0; off >>= 1)
            m = fmaxf(m, __shfl_xor_sync(0xffffffffu, m, off));
        float sr = 0.f;
        #pragma unroll
        for (int q = 0; q < 8; q++) {
            fv[q] = (fv[q] == -INFINITY) ? 0.f : __expf(fv[q] - m);
            sr += fv[q];
        }
        #pragma unroll
        for (int off = 16; off > 0; off >>= 1)
            sr += __shfl_xor_sync(0xffffffffu, sr, off);
        float inv = 1.f / sr;
        #pragma unroll
        for (int q = 0; q < 8; q++) {
            int e = t + 32 * q;
            if (e < AA) out[b * AA + e] = fv[q] * inv;
        }
    }
}

extern "C" void kernel_launch(void* const* d_in, const int* in_sizes, int n_in,
                              void* d_out, int out_size) {
    const float* nf     = (const float*)d_in[0];
    const float* mask   = (const float*)d_in[2];
    const float* Wfcv1  = (const float*)d_in[3];
    const float* bfcv1  = (const float*)d_in[4];
    const float* Wfcv2  = (const float*)d_in[5];
    const float* bfcv2  = (const float*)d_in[6];
    const float* Wa2    = (const float*)d_in[7];
    const float* ba2    = (const float*)d_in[8];
    const float* Wfin   = (const float*)d_in[9];
    const float* bfin   = (const float*)d_in[10];
    const int*   idxm   = (const int*)d_in[11];
    float* out = (float*)d_out;

    apm_gemm_kernel<<<4 * NB, 256>>>(nf, Wa2);
    apm_tail_kernel<<<NB, 256>>>(nf, mask, Wfcv1, bfcv1, Wfcv2, bfcv2,
                                 ba2, Wfin, bfin, idxm, out);
}